// round 2
// baseline (speedup 1.0000x reference)
#include <cuda_runtime.h>
#include <cstdint>
#include <cstddef>

// ===========================================================================
// Compile-time construction of the CTreeC tree topology (DEPTH=7, 255 states,
// 685 edges), including a load-balanced CSR-by-destination layout:
//   - states sorted by in-degree (max in-degree is 7) and assigned to
//     (lane, j) slots so each lane owns 8 states with near-equal edge totals
//   - per-j row lengths padded to the group max (rowmax), padded entries
//     point at dummy slot 255 whose value is always 0
// ===========================================================================
namespace ct {

constexpr int DEPTH  = 7;
constexpr int NS     = (1 << (DEPTH + 1)) - 1;   // 255
constexpr int NE_MAX = 700;                       // actual: 685

struct Lists { int l[DEPTH + 1]; int r[DEPTH + 1]; int n; int last; };

struct Graph {
  int  ne;
  int  esrc[NE_MAX];
  int  edst[NE_MAX];
  bool is_start[NS];
  bool is_end[NS];
};

constexpr Lists build(int depth, int start, Graph& g) {
  Lists res{};
  if (depth == 0) { res.l[0] = start; res.r[0] = start; res.n = 1; res.last = start; return res; }
  Lists L = build(depth - 1, start, g);
  int my = L.last + 1;
  Lists R = build(depth - 1, my + 1, g);
  for (int i = 0; i < L.n; i++)
    for (int j = 0; j < R.n; j++) { g.esrc[g.ne] = L.r[i]; g.edst[g.ne] = R.l[j]; g.ne++; }
  res.l[0] = my; res.r[0] = my;
  for (int i = 0; i < L.n; i++) { res.l[i + 1] = L.l[i]; res.r[i + 1] = R.r[i]; }
  res.n = L.n + 1; res.last = R.last;
  return res;
}

constexpr Graph make_graph() {
  Graph g{};
  Lists root = build(DEPTH, 0, g);
  for (int i = 0; i <= DEPTH; i++) { g.is_start[root.l[i]] = true; g.is_end[root.r[i]] = true; }
  return g;
}

struct Plan {
  int rowmax[8];
  int off[9];
  int total;
  int state_of_slot[256];    // -1 for the dummy slot
  int slot_of_state[NS];
  int gidx[32 * 32];         // [(off[j]+k)*32 + lane] = source SLOT (255 = pad)
  unsigned start_mask[32];   // bit j set if slot lane*8+j is a start state
  unsigned end_mask[32];     // bit j set if slot lane*8+j is an end state
};

constexpr Plan make_plan() {
  Plan P{};
  Graph g = make_graph();

  int indeg[NS] = {};
  for (int e = 0; e < g.ne; e++) indeg[g.edst[e]]++;

  // insertion sort states by in-degree, descending
  int order[NS] = {};
  for (int i = 0; i < NS; i++) order[i] = i;
  for (int i = 1; i < NS; i++) {
    int x = order[i]; int j = i - 1;
    while (j >= 0 && indeg[order[j]] < indeg[x]) { order[j + 1] = order[j]; j--; }
    order[j + 1] = x;
  }

  for (int s = 0; s < 256; s++) P.state_of_slot[s] = -1;
  for (int r = 0; r < NS; r++) {
    int lane = r % 32, j = r / 32;
    int slot = lane * 8 + j;                 // lane owns 8 contiguous slots
    P.state_of_slot[slot] = order[r];
    P.slot_of_state[order[r]] = slot;
  }

  for (int j = 0; j < 8; j++) {
    int m = 0;
    for (int r = 32 * j; r < 32 * j + 32 && r < NS; r++)
      if (indeg[order[r]] > m) m = indeg[order[r]];
    P.rowmax[j] = m;
  }
  P.off[0] = 0;
  for (int j = 0; j < 8; j++) P.off[j + 1] = P.off[j] + P.rowmax[j];
  P.total = P.off[8];

  for (int i = 0; i < P.total * 32; i++) P.gidx[i] = 255;  // pad -> dummy slot
  int fill[256] = {};
  for (int e = 0; e < g.ne; e++) {
    int dslot = P.slot_of_state[g.edst[e]];
    int lane = dslot / 8, j = dslot % 8;
    int k = fill[dslot]++;
    P.gidx[(P.off[j] + k) * 32 + lane] = P.slot_of_state[g.esrc[e]];
  }

  for (int lane = 0; lane < 32; lane++) {
    unsigned sm = 0, em = 0;
    for (int j = 0; j < 8; j++) {
      int st = P.state_of_slot[lane * 8 + j];
      if (st >= 0) {
        if (g.is_start[st]) sm |= (1u << j);
        if (g.is_end[st])   em |= (1u << j);
      }
    }
    P.start_mask[lane] = sm; P.end_mask[lane] = em;
  }
  return P;
}

constexpr Plan PLAN  = make_plan();
constexpr int  TOTAL = PLAN.total;

}  // namespace ct

// Device copies of the tables (statically initialized from constexpr — no
// runtime allocation, no memcpy, graph-safe).
__device__ const ct::Plan d_plan = ct::PLAN;

// Scratch: slot-permuted exp(extracted log-probs), layout [(t*B+b)*256 + slot].
// 64*64*256 floats = 16.8 MB static device array (allocation-free scratch).
__device__ float d_scratch[64 * 64 * 256];

// ===========================================================================
// Kernel 1: extraction + exp.  scratch[(t*B+b)*256 + slot] =
//   exp(log_probs[state(slot), b, targets[t,b]])  for t < len[b], else 0.
// ===========================================================================
__global__ void extract_kernel(const float* __restrict__ lp,
                               const int*   __restrict__ tgt,
                               const int*   __restrict__ lens,
                               int B, int T, int vocab) {
  int idx = blockIdx.x * blockDim.x + threadIdx.x;
  int total = T * B * 256;
  if (idx >= total) return;
  int slot = idx & 255;
  int tb   = idx >> 8;         // == t*B + b
  int b    = tb % B;
  int t    = tb / B;
  float val = 0.0f;
  int st = d_plan.state_of_slot[slot];
  if (st >= 0 && t < lens[b]) {
    int tg = tgt[tb];
    val = expf(lp[((size_t)st * B + b) * (size_t)vocab + tg]);
  }
  d_scratch[idx] = val;
}

// ===========================================================================
// Kernel 2: per-warp forward scan.  One warp per batch element, 8 states per
// lane in registers, edges gathered through a 1KB smem tile per warp.
// Answer = -(M + log(sum over END of c_{len-1})) via exact telescoping.
// ===========================================================================
template <int J>
__device__ __forceinline__ void gather_rows(float (&a)[8], const float* sc,
                                            const int (&gi)[ct::TOTAL]) {
  if constexpr (J < 8) {
    constexpr int rm = ct::PLAN.rowmax[J];
    constexpr int o  = ct::PLAN.off[J];
    float acc = 0.0f;
#pragma unroll
    for (int k = 0; k < rm; k++) acc += sc[gi[o + k]];
    a[J] = acc;
    gather_rows<J + 1>(a, sc, gi);
  }
}

constexpr int WPB = 4;  // warps (batch elements) per block

__global__ void __launch_bounds__(WPB * 32, 1)
scan_kernel(const int* __restrict__ lens, float* __restrict__ out, int B, int T) {
  __shared__ float sc_all[WPB][256];
  int widx = threadIdx.x >> 5;
  int lane = threadIdx.x & 31;
  int b = blockIdx.x * WPB + widx;
  if (b >= B) return;
  float* sc = sc_all[widx];

  // preload per-lane edge-source slots into registers (fully unrolled)
  int gi[ct::TOTAL];
#pragma unroll
  for (int q = 0; q < ct::TOTAL; q++) gi[q] = d_plan.gidx[q * 32 + lane];
  unsigned smask = d_plan.start_mask[lane];
  unsigned emask = d_plan.end_mask[lane];

  int len = lens[b];
  if (len < 1) len = 1;
  if (len > T) len = T;

  float p[8];
#pragma unroll
  for (int j = 0; j < 8; j++) p[j] = ((smask >> j) & 1u) ? 1.0f : 0.0f;

  const float* ebase = d_scratch + (size_t)b * 256 + (size_t)lane * 8;
  const size_t estride = (size_t)B * 256;

  float4 ea = *(const float4*)(ebase);
  float4 eb = *(const float4*)(ebase + 4);

  float M = 0.0f;
  float c[8];

  for (int t = 0; t < len; t++) {
    c[0] = p[0] * ea.x; c[1] = p[1] * ea.y; c[2] = p[2] * ea.z; c[3] = p[3] * ea.w;
    c[4] = p[4] * eb.x; c[5] = p[5] * eb.y; c[6] = p[6] * eb.z; c[7] = p[7] * eb.w;

    // prefetch next step's exp-values (hidden behind the scatter below)
    if (t + 1 < len) {
      const float* np = ebase + (size_t)(t + 1) * estride;
      ea = *(const float4*)(np);
      eb = *(const float4*)(np + 4);
    }

    // rescale every 2 steps (warp-shuffle max); keeps values in fp32 range
    if ((t & 1) == 1) {
      float mx = c[0];
#pragma unroll
      for (int j = 1; j < 8; j++) mx = fmaxf(mx, c[j]);
#pragma unroll
      for (int o = 16; o > 0; o >>= 1)
        mx = fmaxf(mx, __shfl_xor_sync(0xffffffffu, mx, o));
      float inv = 1.0f / mx;
      M += logf(mx);
#pragma unroll
      for (int j = 0; j < 8; j++) c[j] *= inv;
    }

    if (t == len - 1) break;   // end contribution uses c, no scatter needed

    // scatter along edges: publish c by slot, then CSR-by-dst gather
#pragma unroll
    for (int j = 0; j < 8; j++) sc[lane * 8 + j] = c[j];
    __syncwarp();
    gather_rows<0>(p, sc, gi);
    __syncwarp();
  }

  // loss = -(M + log( sum over END states of c ))
  float s = 0.0f;
#pragma unroll
  for (int j = 0; j < 8; j++) if ((emask >> j) & 1u) s += c[j];
#pragma unroll
  for (int o = 16; o > 0; o >>= 1) s += __shfl_xor_sync(0xffffffffu, s, o);
  if (lane == 0) out[b] = -(M + logf(s));
}

// ===========================================================================
extern "C" void kernel_launch(void* const* d_in, const int* in_sizes, int n_in,
                              void* d_out, int out_size) {
  const float* lp   = (const float*)d_in[0];   // log_probs (V,B,vocab) f32
  const int*   tgt  = (const int*)d_in[1];     // targets (T,B) i32
  const int*   lens = (const int*)d_in[2];     // target_lengths (B,) i32
  float* out = (float*)d_out;

  int B = in_sizes[2];
  int T = in_sizes[1] / B;
  int vocab = in_sizes[0] / (ct::NS * B);

  int total = T * B * 256;
  extract_kernel<<<(total + 255) / 256, 256>>>(lp, tgt, lens, B, T, vocab);
  scan_kernel<<<(B + WPB - 1) / WPB, WPB * 32>>>(lens, out, B, T);
}

// round 3
// speedup vs baseline: 1.4491x; 1.4491x over previous
#include <cuda_runtime.h>
#include <cstdint>
#include <cstddef>

// ===========================================================================
// Compile-time CTreeC topology (DEPTH=7, 255 states, 685 edges) with a
// bank-conflict-minimized CSR-by-destination gather schedule:
//   - states sorted by in-degree, assigned to (lane, j) slots (8 per lane)
//   - per-j rows padded to group max; within each gather column, a constexpr
//     greedy picks per-lane sources to minimize smem bank collisions
//   - pad entries point at per-lane zero slots 256+lane (bank == lane)
// ===========================================================================
namespace ct {

constexpr int DEPTH  = 7;
constexpr int NS     = (1 << (DEPTH + 1)) - 1;   // 255
constexpr int NE_MAX = 700;                       // actual: 685

struct Lists { int l[DEPTH + 1]; int r[DEPTH + 1]; int n; int last; };

struct Graph {
  int  ne;
  int  esrc[NE_MAX];
  int  edst[NE_MAX];
  bool is_start[NS];
  bool is_end[NS];
};

constexpr Lists build(int depth, int start, Graph& g) {
  Lists res{};
  if (depth == 0) { res.l[0] = start; res.r[0] = start; res.n = 1; res.last = start; return res; }
  Lists L = build(depth - 1, start, g);
  int my = L.last + 1;
  Lists R = build(depth - 1, my + 1, g);
  for (int i = 0; i < L.n; i++)
    for (int j = 0; j < R.n; j++) { g.esrc[g.ne] = L.r[i]; g.edst[g.ne] = R.l[j]; g.ne++; }
  res.l[0] = my; res.r[0] = my;
  for (int i = 0; i < L.n; i++) { res.l[i + 1] = L.l[i]; res.r[i + 1] = R.r[i]; }
  res.n = L.n + 1; res.last = R.last;
  return res;
}

constexpr Graph make_graph() {
  Graph g{};
  Lists root = build(DEPTH, 0, g);
  for (int i = 0; i <= DEPTH; i++) { g.is_start[root.l[i]] = true; g.is_end[root.r[i]] = true; }
  return g;
}

struct Plan {
  int rowmax[8];
  int off[9];
  int total;
  int state_of_slot[256];    // -1 for the dummy slot
  int slot_of_state[NS];
  int gidx[32 * 32];         // [(off[j]+k)*32 + lane] = source SLOT (256+lane = pad)
  unsigned start_mask[32];
  unsigned end_mask[32];
};

constexpr Plan make_plan() {
  Plan P{};
  Graph g = make_graph();

  int indeg[NS] = {};
  for (int e = 0; e < g.ne; e++) indeg[g.edst[e]]++;

  // insertion sort states by in-degree, descending
  int order[NS] = {};
  for (int i = 0; i < NS; i++) order[i] = i;
  for (int i = 1; i < NS; i++) {
    int x = order[i]; int j = i - 1;
    while (j >= 0 && indeg[order[j]] < indeg[x]) { order[j + 1] = order[j]; j--; }
    order[j + 1] = x;
  }

  for (int s = 0; s < 256; s++) P.state_of_slot[s] = -1;
  for (int r = 0; r < NS; r++) {
    int lane = r % 32, j = r / 32;
    int slot = lane * 8 + j;
    P.state_of_slot[slot] = order[r];
    P.slot_of_state[order[r]] = slot;
  }

  // per-destination-slot source lists
  int srcs[256][8] = {};
  int cnt[256] = {};
  for (int e = 0; e < g.ne; e++) {
    int ds = P.slot_of_state[g.edst[e]];
    srcs[ds][cnt[ds]++] = P.slot_of_state[g.esrc[e]];
  }

  for (int j = 0; j < 8; j++) {
    int m = 0;
    for (int lane = 0; lane < 32; lane++)
      if (cnt[lane * 8 + j] > m) m = cnt[lane * 8 + j];
    P.rowmax[j] = m;
  }
  P.off[0] = 0;
  for (int j = 0; j < 8; j++) P.off[j + 1] = P.off[j] + P.rowmax[j];
  P.total = P.off[8];

  // bank-aware greedy column scheduling
  bool used[256][8] = {};
  for (int j = 0; j < 8; j++) {
    for (int k = 0; k < P.rowmax[j]; k++) {
      int bankcnt[32] = {};
      int chosen[32] = {};
      int nch = 0;
      for (int lane = 0; lane < 32; lane++) {
        int ds = lane * 8 + j;
        int best = -1, bestcost = 1 << 30;
        for (int i = 0; i < cnt[ds]; i++) {
          if (used[ds][i]) continue;
          int s = srcs[ds][i];
          int cost = bankcnt[s & 31];
          for (int q = 0; q < nch; q++) if (chosen[q] == s) { cost = -1; }
          if (cost < bestcost) { bestcost = cost; best = i; }
        }
        int pos = (P.off[j] + k) * 32 + lane;
        if (best >= 0) {
          int s = srcs[ds][best];
          used[ds][best] = true;
          P.gidx[pos] = s;
          bool dup = false;
          for (int q = 0; q < nch; q++) if (chosen[q] == s) dup = true;
          if (!dup) { bankcnt[s & 31]++; chosen[nch++] = s; }
        } else {
          P.gidx[pos] = 256 + lane;   // per-lane zero pad, bank == lane
        }
      }
    }
  }

  for (int lane = 0; lane < 32; lane++) {
    unsigned sm = 0, em = 0;
    for (int j = 0; j < 8; j++) {
      int st = P.state_of_slot[lane * 8 + j];
      if (st >= 0) {
        if (g.is_start[st]) sm |= (1u << j);
        if (g.is_end[st])   em |= (1u << j);
      }
    }
    P.start_mask[lane] = sm; P.end_mask[lane] = em;
  }
  return P;
}

constexpr Plan PLAN  = make_plan();
constexpr int  TOTAL = PLAN.total;

}  // namespace ct

__device__ const ct::Plan d_plan = ct::PLAN;

// Scratch: slot-permuted exp(extracted log-probs), layout [b][t][slot]
// (contiguous per batch element for the scan kernel's smem preload).
__device__ float d_scratch[64 * 64 * 256];

// ===========================================================================
// Kernel 1: extraction + exp.
//   scratch[(b*T + t)*256 + slot] = exp(log_probs[state(slot), b, targets[t,b]])
// ===========================================================================
__global__ void extract_kernel(const float* __restrict__ lp,
                               const int*   __restrict__ tgt,
                               int B, int T, int vocab) {
  int idx = blockIdx.x * blockDim.x + threadIdx.x;
  int total = T * B * 256;
  if (idx >= total) return;
  int slot = idx & 255;
  int bt   = idx >> 8;          // == b*T + t
  int t    = bt % T;
  int b    = bt / T;
  float val = 0.0f;
  int st = d_plan.state_of_slot[slot];
  if (st >= 0) {
    int tg = tgt[t * B + b];
    val = expf(lp[((size_t)st * B + b) * (size_t)vocab + tg]);
  }
  d_scratch[idx] = val;
}

// ===========================================================================
// Kernel 2: per-warp forward scan, fully smem-resident.
// ===========================================================================
template <int J>
__device__ __forceinline__ void gather_rows(float (&a)[8], const float* sc,
                                            const int (&gi)[ct::TOTAL]) {
  if constexpr (J < 8) {
    constexpr int rm = ct::PLAN.rowmax[J];
    constexpr int o  = ct::PLAN.off[J];
    if constexpr (rm == 0) {
      a[J] = 0.0f;
    } else {
      float v[rm];
#pragma unroll
      for (int k = 0; k < rm; k++) v[k] = sc[gi[o + k]];
#pragma unroll
      for (int s2 = 1; s2 < rm; s2 *= 2)
#pragma unroll
        for (int k = 0; k + s2 < rm; k += 2 * s2) v[k] += v[k + s2];
      a[J] = v[0];
    }
    gather_rows<J + 1>(a, sc, gi);
  }
}

constexpr int PRE_THREADS = 128;

extern __shared__ float dyn_smem[];

__global__ void __launch_bounds__(PRE_THREADS, 1)
scan_kernel(const int* __restrict__ lens, float* __restrict__ out, int B, int T) {
  int b = blockIdx.x;
  float* es  = dyn_smem;            // T * 256 exp-values for this batch element
  float* sc0 = dyn_smem + T * 256;  // 288-float publish tile (double buffered)
  float* sc1 = sc0 + 288;

  // cooperative preload of the whole e-stream (contiguous)
  {
    const float4* src = (const float4*)(d_scratch + (size_t)b * T * 256);
    float4* dst = (float4*)es;
    int n4 = T * 64;
    for (int i = threadIdx.x; i < n4; i += PRE_THREADS) dst[i] = src[i];
  }
  __syncthreads();
  if (threadIdx.x >= 32) return;
  int lane = threadIdx.x;

  sc0[256 + lane] = 0.0f;           // per-lane zero pads
  sc1[256 + lane] = 0.0f;

  int gi[ct::TOTAL];
#pragma unroll
  for (int q = 0; q < ct::TOTAL; q++) gi[q] = d_plan.gidx[q * 32 + lane];
  unsigned smask = d_plan.start_mask[lane];
  unsigned emask = d_plan.end_mask[lane];

  int len = lens[b];
  if (len < 1) len = 1;
  if (len > T) len = T;

  float p[8];
#pragma unroll
  for (int j = 0; j < 8; j++) p[j] = ((smask >> j) & 1u) ? 1.0f : 0.0f;

  float M = 0.0f;
  float inv_next = 1.0f, logm_next = 0.0f;   // deferred renorm (applied 2 steps late)
  float c[8];

  float4 ea = *(const float4*)(es + lane * 8);
  float4 eb = *(const float4*)(es + lane * 8 + 4);

#pragma unroll 2
  for (int t = 0; t < len; t++) {
    const bool odd = (t & 1) != 0;

    c[0] = p[0] * ea.x; c[1] = p[1] * ea.y; c[2] = p[2] * ea.z; c[3] = p[3] * ea.w;
    c[4] = p[4] * eb.x; c[5] = p[5] * eb.y; c[6] = p[6] * eb.z; c[7] = p[7] * eb.w;
    if (odd) {
#pragma unroll
      for (int j = 0; j < 8; j++) c[j] *= inv_next;
      M += logm_next;
    }

    // prefetch next step's e (LDS, one step ahead — latency hidden)
    {
      int tn = (t + 1 < len) ? (t + 1) : t;
      const float* np = es + tn * 256 + lane * 8;
      ea = *(const float4*)np;
      eb = *(const float4*)(np + 4);
    }

    if (t == len - 1) break;

    float* sc = odd ? sc1 : sc0;
    *(float4*)(sc + lane * 8)     = make_float4(c[0], c[1], c[2], c[3]);
    *(float4*)(sc + lane * 8 + 4) = make_float4(c[4], c[5], c[6], c[7]);
    __syncwarp();

    if (odd) {
      // off-critical-path warp max; result consumed at step t+2
      float mx = fmaxf(fmaxf(fmaxf(c[0], c[1]), fmaxf(c[2], c[3])),
                       fmaxf(fmaxf(c[4], c[5]), fmaxf(c[6], c[7])));
#pragma unroll
      for (int o = 16; o > 0; o >>= 1)
        mx = fmaxf(mx, __shfl_xor_sync(0xffffffffu, mx, o));
      inv_next  = 1.0f / mx;
      logm_next = logf(mx);
    }

    gather_rows<0>(p, sc, gi);
    // no second syncwarp needed: publish tiles are double-buffered
  }

  float s = 0.0f;
#pragma unroll
  for (int j = 0; j < 8; j++) if ((emask >> j) & 1u) s += c[j];
#pragma unroll
  for (int o = 16; o > 0; o >>= 1) s += __shfl_xor_sync(0xffffffffu, s, o);
  if (lane == 0) out[b] = -(M + logf(s));
}

// ===========================================================================
extern "C" void kernel_launch(void* const* d_in, const int* in_sizes, int n_in,
                              void* d_out, int out_size) {
  const float* lp   = (const float*)d_in[0];   // log_probs (V,B,vocab) f32
  const int*   tgt  = (const int*)d_in[1];     // targets (T,B) i32
  const int*   lens = (const int*)d_in[2];     // target_lengths (B,) i32
  float* out = (float*)d_out;

  int B = in_sizes[2];
  int T = in_sizes[1] / B;
  int vocab = in_sizes[0] / (ct::NS * B);

  int total = T * B * 256;
  extract_kernel<<<(total + 255) / 256, 256>>>(lp, tgt, B, T, vocab);

  size_t shbytes = ((size_t)T * 256 + 2 * 288) * sizeof(float);
  cudaFuncSetAttribute(scan_kernel, cudaFuncAttributeMaxDynamicSharedMemorySize,
                       (int)shbytes);
  scan_kernel<<<B, PRE_THREADS, shbytes>>>(lens, out, B, T);
}

// round 7
// speedup vs baseline: 2.0964x; 1.4467x over previous
#include <cuda_runtime.h>
#include <cstdint>
#include <cstddef>

// ===========================================================================
// Compile-time CTreeC topology (DEPTH=7, 255 states, 685 edges) with a
// bank-conflict-minimized CSR-by-destination gather schedule.
// ===========================================================================
namespace ct {

constexpr int DEPTH  = 7;
constexpr int NS     = (1 << (DEPTH + 1)) - 1;   // 255
constexpr int NE_MAX = 700;                       // actual: 685

struct Lists { int l[DEPTH + 1]; int r[DEPTH + 1]; int n; int last; };

struct Graph {
  int  ne;
  int  esrc[NE_MAX];
  int  edst[NE_MAX];
  bool is_start[NS];
  bool is_end[NS];
};

constexpr Lists build(int depth, int start, Graph& g) {
  Lists res{};
  if (depth == 0) { res.l[0] = start; res.r[0] = start; res.n = 1; res.last = start; return res; }
  Lists L = build(depth - 1, start, g);
  int my = L.last + 1;
  Lists R = build(depth - 1, my + 1, g);
  for (int i = 0; i < L.n; i++)
    for (int j = 0; j < R.n; j++) { g.esrc[g.ne] = L.r[i]; g.edst[g.ne] = R.l[j]; g.ne++; }
  res.l[0] = my; res.r[0] = my;
  for (int i = 0; i < L.n; i++) { res.l[i + 1] = L.l[i]; res.r[i + 1] = R.r[i]; }
  res.n = L.n + 1; res.last = R.last;
  return res;
}

constexpr Graph make_graph() {
  Graph g{};
  Lists root = build(DEPTH, 0, g);
  for (int i = 0; i <= DEPTH; i++) { g.is_start[root.l[i]] = true; g.is_end[root.r[i]] = true; }
  return g;
}

struct Plan {
  int rowmax[8];
  int off[9];
  int total;
  int state_of_slot[256];    // -1 for the dummy slot
  int slot_of_state[NS];
  int gidx[32 * 32];         // [(off[j]+k)*32 + lane] = source SLOT (256+lane = pad)
  unsigned start_mask[32];
  unsigned end_mask[32];
};

constexpr Plan make_plan() {
  Plan P{};
  Graph g = make_graph();

  int indeg[NS] = {};
  for (int e = 0; e < g.ne; e++) indeg[g.edst[e]]++;

  int order[NS] = {};
  for (int i = 0; i < NS; i++) order[i] = i;
  for (int i = 1; i < NS; i++) {
    int x = order[i]; int j = i - 1;
    while (j >= 0 && indeg[order[j]] < indeg[x]) { order[j + 1] = order[j]; j--; }
    order[j + 1] = x;
  }

  for (int s = 0; s < 256; s++) P.state_of_slot[s] = -1;
  for (int r = 0; r < NS; r++) {
    int lane = r % 32, j = r / 32;
    int slot = lane * 8 + j;
    P.state_of_slot[slot] = order[r];
    P.slot_of_state[order[r]] = slot;
  }

  int srcs[256][8] = {};
  int cnt[256] = {};
  for (int e = 0; e < g.ne; e++) {
    int ds = P.slot_of_state[g.edst[e]];
    srcs[ds][cnt[ds]++] = P.slot_of_state[g.esrc[e]];
  }

  for (int j = 0; j < 8; j++) {
    int m = 0;
    for (int lane = 0; lane < 32; lane++)
      if (cnt[lane * 8 + j] > m) m = cnt[lane * 8 + j];
    P.rowmax[j] = m;
  }
  P.off[0] = 0;
  for (int j = 0; j < 8; j++) P.off[j + 1] = P.off[j] + P.rowmax[j];
  P.total = P.off[8];

  // bank-aware greedy column scheduling
  bool used[256][8] = {};
  for (int j = 0; j < 8; j++) {
    for (int k = 0; k < P.rowmax[j]; k++) {
      int bankcnt[32] = {};
      int chosen[32] = {};
      int nch = 0;
      for (int lane = 0; lane < 32; lane++) {
        int ds = lane * 8 + j;
        int best = -1, bestcost = 1 << 30;
        for (int i = 0; i < cnt[ds]; i++) {
          if (used[ds][i]) continue;
          int s = srcs[ds][i];
          int cost = bankcnt[s & 31];
          for (int q = 0; q < nch; q++) if (chosen[q] == s) { cost = -1; }
          if (cost < bestcost) { bestcost = cost; best = i; }
        }
        int pos = (P.off[j] + k) * 32 + lane;
        if (best >= 0) {
          int s = srcs[ds][best];
          used[ds][best] = true;
          P.gidx[pos] = s;
          bool dup = false;
          for (int q = 0; q < nch; q++) if (chosen[q] == s) dup = true;
          if (!dup) { bankcnt[s & 31]++; chosen[nch++] = s; }
        } else {
          P.gidx[pos] = 256 + lane;   // per-lane zero pad, bank == lane (self-read)
        }
      }
    }
  }

  for (int lane = 0; lane < 32; lane++) {
    unsigned sm = 0, em = 0;
    for (int j = 0; j < 8; j++) {
      int st = P.state_of_slot[lane * 8 + j];
      if (st >= 0) {
        if (g.is_start[st]) sm |= (1u << j);
        if (g.is_end[st])   em |= (1u << j);
      }
    }
    P.start_mask[lane] = sm; P.end_mask[lane] = em;
  }
  return P;
}

constexpr Plan PLAN  = make_plan();
constexpr int  TOTAL = PLAN.total;     // 25

}  // namespace ct

__device__ const ct::Plan d_plan = ct::PLAN;

// Scratch: slot-permuted exp(extracted log-probs), layout [b][t][slot].
__device__ float d_scratch[64 * 64 * 256];

// ===========================================================================
// Kernel 1: extraction + exp, gated on target length (warp-uniform exit).
// ===========================================================================
__global__ void extract_kernel(const float* __restrict__ lp,
                               const int*   __restrict__ tgt,
                               const int*   __restrict__ lens,
                               int B, int T, int vocab) {
  int idx = blockIdx.x * blockDim.x + threadIdx.x;
  if (idx >= T * B * 256) return;
  int slot = idx & 255;
  int bt   = idx >> 8;          // == b*T + t
  int t    = bt % T;
  int b    = bt / T;
  if (t >= lens[b]) return;     // uniform across the warp (32 slots of one (b,t))
  int st = d_plan.state_of_slot[slot];
  float val = 0.0f;
  if (st >= 0) {
    int tg = tgt[t * B + b];
    val = __expf(lp[((size_t)st * B + b) * (size_t)vocab + tg]);
  }
  d_scratch[idx] = val;
}

// ===========================================================================
// Kernel 2: per-warp forward scan (warp 0 of a 128-thread block per batch
// element; threads 32..127 only help with the smem preload).
// ===========================================================================
template <int OFS>
__device__ __forceinline__ void publish_c(unsigned wa, const float (&c)[8]) {
  asm volatile("st.shared.v4.f32 [%0+%1], {%2,%3,%4,%5};"
      :: "r"(wa), "n"(OFS), "f"(c[0]), "f"(c[1]), "f"(c[2]), "f"(c[3]) : "memory");
  asm volatile("st.shared.v4.f32 [%0+%1], {%2,%3,%4,%5};"
      :: "r"(wa), "n"(OFS + 16), "f"(c[4]), "f"(c[5]), "f"(c[6]), "f"(c[7]) : "memory");
}

template <int OFS, int J>
__device__ __forceinline__ void gather_rows(float (&p)[8],
                                            const unsigned (&ga)[ct::TOTAL]) {
  if constexpr (J < 8) {
    constexpr int rm = ct::PLAN.rowmax[J];
    constexpr int o  = ct::PLAN.off[J];
    if constexpr (rm == 0) {
      p[J] = 0.0f;
    } else {
      float v[rm];
#pragma unroll
      for (int k = 0; k < rm; k++)
        asm volatile("ld.shared.f32 %0, [%1+%2];" : "=f"(v[k]) : "r"(ga[o + k]), "n"(OFS));
#pragma unroll
      for (int s2 = 1; s2 < rm; s2 *= 2)
#pragma unroll
        for (int k = 0; k + s2 < rm; k += 2 * s2) v[k] += v[k + s2];
      p[J] = v[0];
    }
    gather_rows<OFS, J + 1>(p, ga);
  }
}

template <int TILE, bool DOMAX>
__device__ __forceinline__ void step_body(float (&p)[8], float4& ea, float4& eb,
                                          const float4*& ep,
                                          const unsigned (&ga)[ct::TOTAL],
                                          unsigned wa, float& mx8) {
  constexpr int OFS = TILE * 1152;
  float c[8];
  c[0] = p[0] * ea.x; c[1] = p[1] * ea.y; c[2] = p[2] * ea.z; c[3] = p[3] * ea.w;
  c[4] = p[4] * eb.x; c[5] = p[5] * eb.y; c[6] = p[6] * eb.z; c[7] = p[7] * eb.w;
  publish_c<OFS>(wa, c);
  if constexpr (DOMAX)
    mx8 = fmaxf(fmaxf(fmaxf(c[0], c[1]), fmaxf(c[2], c[3])),
                fmaxf(fmaxf(c[4], c[5]), fmaxf(c[6], c[7])));
  ea = ep[0]; eb = ep[1]; ep += 64;   // prefetch next step (LDS.128, hidden)
  __syncwarp();
  gather_rows<OFS, 0>(p, ga);
}

__device__ __forceinline__ void run_quad(float (&p)[8], float4& ea, float4& eb,
                                         const float4*& ep,
                                         const unsigned (&ga)[ct::TOTAL],
                                         unsigned wa, float& scale, int& eacc) {
  // apply pending scale (exact power of two)
#pragma unroll
  for (int j = 0; j < 8; j++) p[j] *= scale;
  float mxl = 0.0f;
  step_body<0, false>(p, ea, eb, ep, ga, wa, mxl);
  step_body<1, true >(p, ea, eb, ep, ga, wa, mxl);
  // off-critical-path renorm: single REDUX + exponent extraction
  unsigned mr = __reduce_max_sync(0xffffffffu, __float_as_uint(mxl));
  int e = (int)(mr >> 23) - 127;
  eacc += e;
  scale = __uint_as_float((unsigned)(127 - e) << 23);   // 2^-e (exact)
  step_body<0, false>(p, ea, eb, ep, ga, wa, mxl);
  step_body<1, false>(p, ea, eb, ep, ga, wa, mxl);
}

constexpr int PRE_THREADS = 128;

__global__ void __launch_bounds__(PRE_THREADS, 1)
scan_kernel(const int* __restrict__ lens, float* __restrict__ out, int B, int T) {
  extern __shared__ float dyn[];
  int b = blockIdx.x;

  int len = lens[b];
  if (len < 1) len = 1;
  if (len > T) len = T;

  float* es  = dyn;                     // len * 256 exp-values
  float* scp = dyn + (size_t)T * 256;   // two 288-float publish tiles

  // cooperative preload (contiguous float4s, only len*1KB)
  {
    const float4* src = (const float4*)(d_scratch + (size_t)b * T * 256);
    float4* dst = (float4*)es;
    int n4 = len * 64;
    for (int i = threadIdx.x; i < n4; i += PRE_THREADS) dst[i] = src[i];
  }
  __syncthreads();
  if (threadIdx.x >= 32) return;
  int lane = threadIdx.x;

  unsigned sc0a = (unsigned)__cvta_generic_to_shared(scp);

  unsigned ga[ct::TOTAL];
#pragma unroll
  for (int q = 0; q < ct::TOTAL; q++)
    ga[q] = sc0a + (unsigned)d_plan.gidx[q * 32 + lane] * 4u;
  unsigned wa = sc0a + (unsigned)lane * 32u;
  scp[256 + lane]       = 0.0f;   // per-lane zero pad, tile 0 (self-read only)
  scp[288 + 256 + lane] = 0.0f;   // per-lane zero pad, tile 1
  unsigned smask = d_plan.start_mask[lane];
  unsigned emask = d_plan.end_mask[lane];

  float p[8];
#pragma unroll
  for (int j = 0; j < 8; j++) p[j] = ((smask >> j) & 1u) ? 1.0f : 0.0f;

  const float4* ep = (const float4*)(es + lane * 8);
  float4 ea = ep[0], eb = ep[1];
  ep += 64;

  int nfull = (len - 1) >> 2;
  int rem   = (len - 1) & 3;

  float scale = 1.0f;
  int eacc = 0;
  float dummy;

  for (int q = 0; q < nfull; q++) run_quad(p, ea, eb, ep, ga, wa, scale, eacc);

  // apply last pending scale
#pragma unroll
  for (int j = 0; j < 8; j++) p[j] *= scale;

  if (rem >= 1) step_body<0, false>(p, ea, eb, ep, ga, wa, dummy);
  if (rem >= 2) step_body<1, false>(p, ea, eb, ep, ga, wa, dummy);
  if (rem >= 3) step_body<0, false>(p, ea, eb, ep, ga, wa, dummy);

  // final step (t = len-1): no scatter, reduce over END states
  float c[8];
  c[0] = p[0] * ea.x; c[1] = p[1] * ea.y; c[2] = p[2] * ea.z; c[3] = p[3] * ea.w;
  c[4] = p[4] * eb.x; c[5] = p[5] * eb.y; c[6] = p[6] * eb.z; c[7] = p[7] * eb.w;

  float s = 0.0f;
#pragma unroll
  for (int j = 0; j < 8; j++) if ((emask >> j) & 1u) s += c[j];
#pragma unroll
  for (int o = 16; o > 0; o >>= 1) s += __shfl_xor_sync(0xffffffffu, s, o);
  if (lane == 0)
    out[b] = -((float)eacc * 0.69314718055994531f + logf(s));
}

// ===========================================================================
extern "C" void kernel_launch(void* const* d_in, const int* in_sizes, int n_in,
                              void* d_out, int out_size) {
  const float* lp   = (const float*)d_in[0];   // log_probs (V,B,vocab) f32
  const int*   tgt  = (const int*)d_in[1];     // targets (T,B) i32
  const int*   lens = (const int*)d_in[2];     // target_lengths (B,) i32
  float* out = (float*)d_out;

  int B = in_sizes[2];
  int T = in_sizes[1] / B;
  int vocab = in_sizes[0] / (ct::NS * B);

  int total = T * B * 256;
  extract_kernel<<<(total + 255) / 256, 256>>>(lp, tgt, lens, B, T, vocab);

  size_t shbytes = ((size_t)T * 256 + 2 * 288) * sizeof(float);
  cudaFuncSetAttribute(scan_kernel, cudaFuncAttributeMaxDynamicSharedMemorySize,
                       (int)shbytes);
  scan_kernel<<<B, PRE_THREADS, shbytes>>>(lens, out, B, T);
}